// round 12
// baseline (speedup 1.0000x reference)
#include <cuda_runtime.h>
#include <cuda_bf16.h>
#include <cstdint>

// ---------------------------------------------------------------------------
// GIN encoder, deterministic. GEMM1/GEMM2: 256x128 tiles, 512 threads,
// mma.sync bf16 hi/lo (3-MMA), cp.async, ldmatrix. GEMM2 fuses BN partials.
// Gather: warp-per-node float4, 4-edge unroll. BN pre-applied (bnrelu).
// ---------------------------------------------------------------------------
#define N_NODES 50000
#define M_PAD   50176           // 196*256
#define EMB     300
#define EMB2    600
#define N_EDGES 800000
#define NLAYER  5
#define NCHUNK  196             // BN row chunks of 256 (= GEMM2 M-tiles)
#define NBLK256 196

#define KP1 320
#define NP1 640
#define KP2 608
#define NP2 384

__device__ float g_h   [M_PAD * EMB];     // gather source (node emb / bn(h))
__device__ float g_agg [M_PAD * EMB];     // GEMM2 out / BN in
__device__ __align__(16) __nv_bfloat16 g_aggh[M_PAD * KP1];
__device__ __align__(16) __nv_bfloat16 g_aggl[M_PAD * KP1];
__device__ __align__(16) __nv_bfloat16 g_hidh[M_PAD * KP2];
__device__ __align__(16) __nv_bfloat16 g_hidl[M_PAD * KP2];
__device__ float g_stats[2 * EMB];
__device__ float g_part [NCHUNK * 2 * EMB];
__device__ int   g_deg [N_NODES];
__device__ int   g_cur [N_NODES];
__device__ int   g_cnt [N_NODES * 9];
__device__ int   g_off [N_NODES + 1];
__device__ int   g_src [N_EDGES];
__device__ int   g_bsum[256];
__device__ __align__(16) __nv_bfloat16 g_w1h[NLAYER * NP1 * KP1];
__device__ __align__(16) __nv_bfloat16 g_w1l[NLAYER * NP1 * KP1];
__device__ __align__(16) __nv_bfloat16 g_w2h[NLAYER * NP2 * KP2];
__device__ __align__(16) __nv_bfloat16 g_w2l[NLAYER * NP2 * KP2];

#define MMA16816(d, a, b0, b1)                                                \
    asm volatile("mma.sync.aligned.m16n8k16.row.col.f32.bf16.bf16.f32 "       \
        "{%0,%1,%2,%3}, {%4,%5,%6,%7}, {%8,%9}, {%0,%1,%2,%3};"               \
        : "+f"((d)[0]), "+f"((d)[1]), "+f"((d)[2]), "+f"((d)[3])              \
        : "r"((a)[0]), "r"((a)[1]), "r"((a)[2]), "r"((a)[3]),                 \
          "r"(b0), "r"(b1))

#define LDSM_X4(r, addr)                                                      \
    asm volatile("ldmatrix.sync.aligned.m8n8.x4.shared.b16 {%0,%1,%2,%3}, [%4];" \
        : "=r"((r)[0]), "=r"((r)[1]), "=r"((r)[2]), "=r"((r)[3]) : "r"(addr))

__device__ __forceinline__ void cpa16(uint32_t dst, const void* src) {
    asm volatile("cp.async.cg.shared.global [%0], [%1], 16;" :: "r"(dst), "l"(src));
}
#define CPA_COMMIT() asm volatile("cp.async.commit_group;" ::: "memory")
#define CPA_WAIT(n)  asm volatile("cp.async.wait_group %0;" :: "n"(n) : "memory")

__device__ __forceinline__ uint32_t smem_u32(const void* p) {
    uint32_t a;
    asm("{ .reg .u64 t; cvta.to.shared.u64 t, %1; cvt.u32.u64 %0, t; }" : "=r"(a) : "l"(p));
    return a;
}
__device__ __forceinline__ uint32_t packbf(float lo, float hi) {
    uint32_t r;
    asm("cvt.rn.bf16x2.f32 %0, %1, %2;" : "=r"(r) : "f"(hi), "f"(lo));
    return r;
}
__device__ __forceinline__ void split2(float x, float y, uint32_t& hi, uint32_t& lo) {
    __nv_bfloat16 hx = __float2bfloat16(x), hy = __float2bfloat16(y);
    hi = ((uint32_t)__bfloat16_as_ushort(hy) << 16) | __bfloat16_as_ushort(hx);
    lo = packbf(x - __bfloat162float(hx), y - __bfloat162float(hy));
}

// ---------------------------------------------------------------------------
__global__ void node_emb_kernel(const int* __restrict__ x,
                                const float* __restrict__ xemb) {
    int idx = blockIdx.x * blockDim.x + threadIdx.x;
    if (idx >= N_NODES * 75) return;
    int row = idx / 75;
    int c4  = idx - row * 75;
    int a = x[2 * row];
    int b = x[2 * row + 1];
    float4 va = ((const float4*)(xemb + a * EMB))[c4];
    float4 vb = ((const float4*)(xemb + b * EMB))[c4];
    va.x += vb.x; va.y += vb.y; va.z += vb.z; va.w += vb.w;
    ((float4*)g_h)[idx] = va;
}

// ---------------------------------------------------------------------------
__global__ void prep_w1_kernel(const float* __restrict__ W1) {
    int idx = blockIdx.x * blockDim.x + threadIdx.x;
    if (idx >= NLAYER * NP1 * KP1) return;
    int layer = idx / (NP1 * KP1);
    int rem = idx - layer * NP1 * KP1;
    int n = rem / KP1, k = rem - n * KP1;
    float v = (n < EMB2 && k < EMB) ? W1[layer * EMB * EMB2 + k * EMB2 + n] : 0.f;
    __nv_bfloat16 h = __float2bfloat16(v);
    g_w1h[idx] = h;
    g_w1l[idx] = __float2bfloat16(v - __bfloat162float(h));
}
__global__ void prep_w2_kernel(const float* __restrict__ W2) {
    int idx = blockIdx.x * blockDim.x + threadIdx.x;
    if (idx >= NLAYER * NP2 * KP2) return;
    int layer = idx / (NP2 * KP2);
    int rem = idx - layer * NP2 * KP2;
    int n = rem / KP2, k = rem - n * KP2;
    float v = (n < EMB && k < EMB2) ? W2[layer * EMB2 * EMB + k * EMB + n] : 0.f;
    __nv_bfloat16 h = __float2bfloat16(v);
    g_w2h[idx] = h;
    g_w2l[idx] = __float2bfloat16(v - __bfloat162float(h));
}

// ---------------------------------------------------------------------------
// CSR build (deterministic)
// ---------------------------------------------------------------------------
__global__ void reset_kernel() {
    int i = blockIdx.x * blockDim.x + threadIdx.x;
    if (i < N_NODES) {
        g_deg[i] = 0; g_cur[i] = 0;
        #pragma unroll
        for (int c = 0; c < 9; c++) g_cnt[i * 9 + c] = 0;
    }
}
__global__ void hist_kernel(const int* __restrict__ ei,
                            const int* __restrict__ ea) {
    int e = blockIdx.x * blockDim.x + threadIdx.x;
    if (e >= N_EDGES) return;
    int dst = ei[N_EDGES + e];
    int c = ea[2 * e] * 3 + ea[2 * e + 1];
    atomicAdd(&g_deg[dst], 1);
    atomicAdd(&g_cnt[dst * 9 + c], 1);
}
__global__ void scan1_kernel() {
    __shared__ int s[256];
    int tid = threadIdx.x;
    int i = blockIdx.x * 256 + tid;
    s[tid] = (i < N_NODES) ? g_deg[i] : 0;
    __syncthreads();
    #pragma unroll
    for (int d = 1; d < 256; d <<= 1) {
        int t = (tid >= d) ? s[tid - d] : 0;
        __syncthreads();
        s[tid] += t;
        __syncthreads();
    }
    if (i < N_NODES) g_off[i + 1] = s[tid];
    if (tid == 255) g_bsum[blockIdx.x] = s[255];
}
__global__ void scan2_kernel() {
    __shared__ int s[256];
    int tid = threadIdx.x;
    s[tid] = (tid < NBLK256) ? g_bsum[tid] : 0;
    __syncthreads();
    #pragma unroll
    for (int d = 1; d < 256; d <<= 1) {
        int t = (tid >= d) ? s[tid - d] : 0;
        __syncthreads();
        s[tid] += t;
        __syncthreads();
    }
    g_bsum[tid] = s[tid];
}
__global__ void scan3_kernel() {
    int i = blockIdx.x * 256 + threadIdx.x;
    if (i < N_NODES && blockIdx.x > 0) g_off[i + 1] += g_bsum[blockIdx.x - 1];
    if (i == 0) g_off[0] = 0;
}
__global__ void fill_kernel(const int* __restrict__ ei) {
    int e = blockIdx.x * blockDim.x + threadIdx.x;
    if (e >= N_EDGES) return;
    int dst = ei[N_EDGES + e];
    int slot = atomicAdd(&g_cur[dst], 1);
    g_src[g_off[dst] + slot] = ei[e];
}
__global__ void sort_kernel() {
    int n = blockIdx.x * blockDim.x + threadIdx.x;
    if (n >= N_NODES) return;
    int a = g_off[n], b = g_off[n + 1];
    for (int i = a + 1; i < b; i++) {
        int key = g_src[i];
        int j = i - 1;
        while (j >= a && g_src[j] > key) { g_src[j + 1] = g_src[j]; j--; }
        g_src[j + 1] = key;
    }
}

// ---------------------------------------------------------------------------
// Gather: warp-per-node, float4 (j = lane + k*32 < 75), 4-edge unroll,
// 8 nodes per warp. No divergence across nodes inside a warp.
// agg[n] = g_h[n] + selfc + sum_c cnt[n][c]*comb[c] + sum_e g_h[src(e)]
// Deterministic: sorted edge order. Output bf16 hi/lo at stride KP1.
// ---------------------------------------------------------------------------
__global__ void __launch_bounds__(256) gather_kernel(const float* __restrict__ eemb,
                                                     int layer) {
    __shared__ __align__(16) float comb[9 * EMB];
    __shared__ __align__(16) float selfc[EMB];
    const float* emb = eemb + layer * 6 * EMB;
    for (int i = threadIdx.x; i < 9 * EMB; i += blockDim.x) {
        int c = i / EMB;
        int d = i - c * EMB;
        comb[i] = emb[(c / 3) * EMB + d] + emb[(c % 3) * EMB + d];
    }
    for (int i = threadIdx.x; i < EMB; i += blockDim.x)
        selfc[i] = emb[4 * EMB + i] + emb[0 * EMB + i];
    __syncthreads();

    int lane = threadIdx.x & 31;
    int wid  = threadIdx.x >> 5;
    const float4* comb4 = (const float4*)comb;
    const float4* sfc4  = (const float4*)selfc;

    for (int g = 0; g < 8; g++) {
        int node = (blockIdx.x * 8 + wid) * 8 + g;   // 64 nodes per block
        if (node >= N_NODES) break;                  // uniform per warp

        float4 acc[3];
        const float4* hn = (const float4*)(g_h + (size_t)node * EMB);
        #pragma unroll
        for (int k = 0; k < 3; k++) {
            int j = lane + k * 32;
            acc[k] = make_float4(0.f, 0.f, 0.f, 0.f);
            if (j < 75) {
                float4 a = hn[j], b = sfc4[j];
                acc[k].x = a.x + b.x; acc[k].y = a.y + b.y;
                acc[k].z = a.z + b.z; acc[k].w = a.w + b.w;
            }
        }
        const int* cnt = g_cnt + node * 9;
        #pragma unroll
        for (int cb = 0; cb < 9; cb++) {
            int cc = cnt[cb];
            if (cc) {
                float cf = (float)cc;
                #pragma unroll
                for (int k = 0; k < 3; k++) {
                    int j = lane + k * 32;
                    if (j < 75) {
                        float4 b = comb4[cb * 75 + j];
                        acc[k].x = fmaf(cf, b.x, acc[k].x);
                        acc[k].y = fmaf(cf, b.y, acc[k].y);
                        acc[k].z = fmaf(cf, b.z, acc[k].z);
                        acc[k].w = fmaf(cf, b.w, acc[k].w);
                    }
                }
            }
        }

        int beg = g_off[node], end = g_off[node + 1];
        int idx = beg;
        for (; idx + 3 < end; idx += 4) {
            int s0 = g_src[idx],     s1 = g_src[idx + 1];
            int s2 = g_src[idx + 2], s3 = g_src[idx + 3];
            const float4* h0 = (const float4*)(g_h + (size_t)s0 * EMB);
            const float4* h1 = (const float4*)(g_h + (size_t)s1 * EMB);
            const float4* h2 = (const float4*)(g_h + (size_t)s2 * EMB);
            const float4* h3 = (const float4*)(g_h + (size_t)s3 * EMB);
            #pragma unroll
            for (int k = 0; k < 3; k++) {
                int j = lane + k * 32;
                if (j < 75) {
                    float4 a = h0[j], b = h1[j], c = h2[j], d = h3[j];
                    acc[k].x += (a.x + b.x) + (c.x + d.x);
                    acc[k].y += (a.y + b.y) + (c.y + d.y);
                    acc[k].z += (a.z + b.z) + (c.z + d.z);
                    acc[k].w += (a.w + b.w) + (c.w + d.w);
                }
            }
        }
        for (; idx < end; idx++) {
            int s0 = g_src[idx];
            const float4* h0 = (const float4*)(g_h + (size_t)s0 * EMB);
            #pragma unroll
            for (int k = 0; k < 3; k++) {
                int j = lane + k * 32;
                if (j < 75) {
                    float4 a = h0[j];
                    acc[k].x += a.x; acc[k].y += a.y;
                    acc[k].z += a.z; acc[k].w += a.w;
                }
            }
        }

        #pragma unroll
        for (int k = 0; k < 3; k++) {
            int j = lane + k * 32;
            if (j < 75) {
                uint32_t h01, l01, h23, l23;
                split2(acc[k].x, acc[k].y, h01, l01);
                split2(acc[k].z, acc[k].w, h23, l23);
                uint2 hv; hv.x = h01; hv.y = h23;
                uint2 lv; lv.x = l01; lv.y = l23;
                *(uint2*)(g_aggh + (size_t)node * KP1 + j * 4) = hv;
                *(uint2*)(g_aggl + (size_t)node * KP1 + j * 4) = lv;
            }
        }
    }
}

// ---------------------------------------------------------------------------
// bnrelu: g_h = relu(bn(g_agg)) once per layer.
// ---------------------------------------------------------------------------
__global__ void bnrelu_kernel() {
    int idx = blockIdx.x * blockDim.x + threadIdx.x;
    if (idx >= N_NODES * 75) return;
    int c = (idx % 75) * 4;
    float4 v = ((const float4*)g_agg)[idx];
    float4 r;
    r.x = fmaxf(fmaf(v.x, g_stats[c + 0], g_stats[EMB + c + 0]), 0.f);
    r.y = fmaxf(fmaf(v.y, g_stats[c + 1], g_stats[EMB + c + 1]), 0.f);
    r.z = fmaxf(fmaf(v.z, g_stats[c + 2], g_stats[EMB + c + 2]), 0.f);
    r.w = fmaxf(fmaf(v.w, g_stats[c + 3], g_stats[EMB + c + 3]), 0.f);
    ((float4*)g_h)[idx] = r;
}

// ---------------------------------------------------------------------------
// Shared GEMM geometry: 256x128 CTA tile, 512 threads, 16 warps (8M x 2N),
// warp tile 32x64, BK=32, cp.async double buffer, ldmatrix loads.
// Stage: A 256x40 bf16 hi+lo (40960B) + B 128x40 hi+lo (20480B) = 61440B.
// ---------------------------------------------------------------------------
#define STG_BYTES 61440
#define OFF_AH 0
#define OFF_AL 20480
#define OFF_BH 40960
#define OFF_BL 51200
#define GEMM_SMEM (2 * STG_BYTES)

// ---------------------------------------------------------------------------
// GEMM1: A = aggh/aggl (KP1=320), B = w1 (NP1), relu, bf16 hi/lo out (KP2).
// ---------------------------------------------------------------------------
__global__ void __launch_bounds__(512, 1) gemm1_kernel(const float* __restrict__ ball,
                                                       int layer) {
    constexpr int NDIM = EMB2, KPAD = KP1, NPAD = NP1, NKB = KP1 / 32;

    extern __shared__ __align__(16) char sm[];
    uint32_t sb = smem_u32(sm);

    int tid  = threadIdx.x;
    int lane = tid & 31;
    int wid  = tid >> 5;
    int wm   = (wid & 7) * 32;
    int wn   = (wid >> 3) * 64;
    int m0   = blockIdx.x * 256;
    int n0   = blockIdx.y * 128;

    int lg = lane >> 3, lj = lane & 7;
    int a_row = (lg & 1) * 8 + lj;
    int a_k8  = (lg >> 1) * 8;
    int b_row = (lg >> 1) * 8 + lj;
    int b_k8  = (lg & 1) * 8;

    float acc[2][8][4];
    #pragma unroll
    for (int mt = 0; mt < 2; mt++)
        #pragma unroll
        for (int nt = 0; nt < 8; nt++)
            #pragma unroll
            for (int q = 0; q < 4; q++) acc[mt][nt][q] = 0.f;

    const size_t bbase = ((size_t)layer * NPAD + n0) * KPAD;

    auto issue = [&](int kb, int st) {
        uint32_t base = sb + st * STG_BYTES;
        #pragma unroll
        for (int i = 0; i < 6; i++) {
            int v = tid + i * 512;                    // 0..3071
            if (v < 2048) {                           // A hi/lo: 256 rows
                int arr = v >> 10;
                int rem = v & 1023;
                int r = rem >> 2, c = rem & 3;
                uint32_t so = (arr ? OFF_AL : OFF_AH) + r * 80 + c * 16;
                size_t ga = (size_t)(m0 + r) * KPAD + kb * 32 + c * 8;
                cpa16(base + so, (arr ? g_aggl : g_aggh) + ga);
            } else {                                  // B hi/lo: 128 rows
                int v2 = v - 2048;
                int arr = v2 >> 9;
                int rem = v2 & 511;
                int r = rem >> 2, c = rem & 3;
                uint32_t so = (arr ? OFF_BL : OFF_BH) + r * 80 + c * 16;
                size_t gb = bbase + (size_t)r * KPAD + kb * 32 + c * 8;
                cpa16(base + so, (arr ? g_w1l : g_w1h) + gb);
            }
        }
        CPA_COMMIT();
    };

    issue(0, 0);

    for (int kb = 0; kb < NKB; kb++) {
        int st = kb & 1;
        CPA_WAIT(0);
        __syncthreads();
        if (kb + 1 < NKB) issue(kb + 1, st ^ 1);

        uint32_t stbase = sb + st * STG_BYTES;
        #pragma unroll
        for (int c = 0; c < 2; c++) {
            uint32_t akoff = (uint32_t)(c * 16 + a_k8) * 2;
            uint32_t bkoff = (uint32_t)(c * 16 + b_k8) * 2;
            uint32_t ah[2][4], al[2][4];
            #pragma unroll
            for (int mt = 0; mt < 2; mt++) {
                uint32_t ra = stbase + (uint32_t)(wm + mt * 16 + a_row) * 80 + akoff;
                LDSM_X4(ah[mt], ra + OFF_AH);
                LDSM_X4(al[mt], ra + OFF_AL);
            }
            #pragma unroll
            for (int ntp = 0; ntp < 4; ntp++) {
                uint32_t rb = stbase + (uint32_t)(wn + ntp * 16 + b_row) * 80 + bkoff;
                uint32_t bh[4], bl[4];
                LDSM_X4(bh, rb + OFF_BH);
                LDSM_X4(bl, rb + OFF_BL);
                #pragma unroll
                for (int sub = 0; sub < 2; sub++) {
                    #pragma unroll
                    for (int mt = 0; mt < 2; mt++) {
                        float* d = acc[mt][ntp * 2 + sub];
                        MMA16816(d, ah[mt], bh[sub * 2], bh[sub * 2 + 1]);
                        MMA16816(d, ah[mt], bl[sub * 2], bl[sub * 2 + 1]);
                        MMA16816(d, al[mt], bh[sub * 2], bh[sub * 2 + 1]);
                    }
                }
            }
        }
    }

    const float* bias = ball + layer * NDIM;
    #pragma unroll
    for (int mt = 0; mt < 2; mt++) {
        #pragma unroll
        for (int hrow = 0; hrow < 2; hrow++) {
            int row = m0 + wm + mt * 16 + (lane >> 2) + hrow * 8;
            #pragma unroll
            for (int nt = 0; nt < 8; nt++) {
                int col = n0 + wn + nt * 8 + (lane & 3) * 2;
                if (col < NDIM) {
                    float v0 = fmaxf(acc[mt][nt][hrow * 2 + 0] + __ldg(bias + col), 0.f);
                    float v1 = fmaxf(acc[mt][nt][hrow * 2 + 1] + __ldg(bias + col + 1), 0.f);
                    uint32_t hi, lo;
                    split2(v0, v1, hi, lo);
                    *(uint32_t*)(g_hidh + (size_t)row * KP2 + col) = hi;
                    *(uint32_t*)(g_hidl + (size_t)row * KP2 + col) = lo;
                }
            }
        }
    }
}

// ---------------------------------------------------------------------------
// GEMM2: A = hidh/hidl (KP2=608), B = w2 (NP2=384), fp32 out + BN partials.
// ---------------------------------------------------------------------------
__global__ void __launch_bounds__(512, 1) gemm2_kernel(const float* __restrict__ ball,
                                                       int layer) {
    constexpr int NDIM = EMB, KPAD = KP2, NPAD = NP2, NKB = KP2 / 32;

    extern __shared__ __align__(16) char sm[];
    uint32_t sb = smem_u32(sm);

    int tid  = threadIdx.x;
    int lane = tid & 31;
    int wid  = tid >> 5;
    int wm   = (wid & 7) * 32;
    int wn   = (wid >> 3) * 64;
    int m0   = blockIdx.x * 256;
    int n0   = blockIdx.y * 128;

    int lg = lane >> 3, lj = lane & 7;
    int a_row = (lg & 1) * 8 + lj;
    int a_k8  = (lg >> 1) * 8;
    int b_row = (lg >> 1) * 8 + lj;
    int b_k8  = (lg & 1) * 8;

    float acc[2][8][4];
    #pragma unroll
    for (int mt = 0; mt < 2; mt++)
        #pragma unroll
        for (int nt = 0; nt < 8; nt++)
            #pragma unroll
            for (int q = 0; q < 4; q++) acc[mt][nt][q] = 0.f;

    const size_t bbase = ((size_t)layer * NPAD + n0) * KPAD;

    auto issue = [&](int kb, int st) {
        uint32_t base = sb + st * STG_BYTES;
        #pragma unroll
        for (int i = 0; i < 6; i++) {
            int v = tid + i * 512;
            if (v < 2048) {
                int arr = v >> 10;
                int rem = v & 1023;
                int r = rem >> 2, c = rem & 3;
                uint32_t so = (arr ? OFF_AL : OFF_AH) + r * 80 + c * 16;
                size_t ga = (size_t)(m0 + r) * KPAD + kb * 32 + c * 8;
                cpa16(base + so, (arr ? g_hidl : g_hidh) + ga);
            } else {
                int v2 = v - 2048;
                int arr = v2 >> 9;
                int rem = v2 & 511;
                int r = rem >> 2, c = rem & 3;
                uint32_t so = (arr ? OFF_BL : OFF_BH) + r * 80 + c * 16;
                size_t gb = bbase + (size_t)r * KPAD + kb * 32 + c * 8;
                cpa16(base + so, (arr ? g_w2l : g_w2h) + gb);
            }
        }
        CPA_COMMIT();
    };

    issue(0, 0);

    for (int kb = 0; kb < NKB; kb++) {
        int st = kb & 1;
        CPA_WAIT(0);
        __syncthreads();
        if (kb + 1 < NKB) issue(kb + 1, st ^ 1);

        uint32_t stbase = sb + st * STG_BYTES;
        #pragma unroll
        for (int c = 0; c < 2; c++) {
            uint32_t akoff = (uint32_t)(c * 16 + a_k8) * 2;
            uint32_t bkoff = (uint32_t)(c * 16 + b_k8) * 2;
            uint32_t ah[2][4], al[2][4];
            #pragma unroll
            for (int mt = 0; mt < 2; mt++) {
                uint32_t ra = stbase + (uint32_t)(wm + mt * 16 + a_row) * 80 + akoff;
                LDSM_X4(ah[mt], ra + OFF_AH);
                LDSM_X4(al[mt], ra + OFF_AL);
            }
            #pragma unroll
            for (int ntp = 0; ntp < 4; ntp++) {
                uint32_t rb = stbase + (uint32_t)(wn + ntp * 16 + b_row) * 80 + bkoff;
                uint32_t bh[4], bl[4];
                LDSM_X4(bh, rb + OFF_BH);
                LDSM_X4(bl, rb + OFF_BL);
                #pragma unroll
                for (int sub = 0; sub < 2; sub++) {
                    #pragma unroll
                    for (int mt = 0; mt < 2; mt++) {
                        float* d = acc[mt][ntp * 2 + sub];
                        MMA16816(d, ah[mt], bh[sub * 2], bh[sub * 2 + 1]);
                        MMA16816(d, ah[mt], bl[sub * 2], bl[sub * 2 + 1]);
                        MMA16816(d, al[mt], bh[sub * 2], bh[sub * 2 + 1]);
                    }
                }
            }
        }
    }

    // --- epilogue: fp32 store + fused BN partials (rows < N_NODES) ---
    __syncthreads();                    // stages dead; reuse smem for reduce
    float* red = (float*)sm;            // [16 warps][8 nt][4 L][4 vals] = 8KB
    const float* bias = ball + layer * NDIM;

    #pragma unroll
    for (int nt = 0; nt < 8; nt++) {
        int col = n0 + wn + nt * 8 + (lane & 3) * 2;
        float bv0 = (col     < NDIM) ? __ldg(bias + col)     : 0.f;
        float bv1 = (col + 1 < NDIM) ? __ldg(bias + col + 1) : 0.f;
        float s0 = 0.f, q0 = 0.f, s1 = 0.f, q1 = 0.f;
        #pragma unroll
        for (int mt = 0; mt < 2; mt++) {
            #pragma unroll
            for (int hrow = 0; hrow < 2; hrow++) {
                int row = m0 + wm + mt * 16 + (lane >> 2) + hrow * 8;
                float v0 = acc[mt][nt][hrow * 2 + 0] + bv0;
                float v1 = acc[mt][nt][hrow * 2 + 1] + bv1;
                if (col < NDIM) {
                    float2 stv; stv.x = v0; stv.y = v1;
                    *(float2*)(g_agg + (size_t)row * EMB + col) = stv;
                }
                if (row < N_NODES) {
                    s0 += v0; q0 += v0 * v0;
                    s1 += v1; q1 += v1 * v1;
                }
            }
        }
        #pragma unroll
        for (int d = 4; d < 32; d <<= 1) {
            s0 += __shfl_xor_sync(0xffffffffu, s0, d);
            q0 += __shfl_xor_sync(0xffffffffu, q0, d);
            s1 += __shfl_xor_sync(0xffffffffu, s1, d);
            q1 += __shfl_xor_sync(0xffffffffu, q1, d);
        }
        if (lane < 4) {
            float* p = red + ((wid * 8 + nt) * 4 + lane) * 4;
            p[0] = s0; p[1] = q0; p[2] = s1; p[3] = q1;
        }
    }
    __syncthreads();
    // final: 64 threads, one per (wn-group, nt, L); sum across 8 M-warps
    if (tid < 64) {
        int wng = tid >> 5, nt = (tid >> 2) & 7, L = tid & 3;
        float s0 = 0.f, q0 = 0.f, s1 = 0.f, q1 = 0.f;
        #pragma unroll
        for (int mw = 0; mw < 8; mw++) {
            int w = wng * 8 + mw;       // wid = (wn-group)*8 + m-warp? NO:
            // wid layout: wm = (wid&7)*32, wn = (wid>>3)*64 -> same wn-group
            // shares wid>>3. So w = wng*8 + mw gives wid&7 = mw, wid>>3 = wng. OK.
            const float* p = red + ((w * 8 + nt) * 4 + L) * 4;
            s0 += p[0]; q0 += p[1]; s1 += p[2]; q1 += p[3];
        }
        int col = n0 + wng * 64 + nt * 8 + L * 2;
        int bx = blockIdx.x;
        if (col < NDIM) {
            g_part[bx * 2 * EMB + col]           = s0;
            g_part[bx * 2 * EMB + EMB + col]     = q0;
            g_part[bx * 2 * EMB + col + 1]       = s1;
            g_part[bx * 2 * EMB + EMB + col + 1] = q1;
        }
    }
}

// ---------------------------------------------------------------------------
__global__ void bn_final_kernel(const float* __restrict__ gamma,
                                const float* __restrict__ beta, int layer) {
    int c = threadIdx.x;
    if (c >= EMB) return;
    float s = 0.f, q = 0.f;
    for (int b = 0; b < NCHUNK; b++) {
        s += g_part[b * 2 * EMB + c];
        q += g_part[b * 2 * EMB + EMB + c];
    }
    const float inv_n = 1.0f / (float)N_NODES;
    float mean = s * inv_n;
    float var  = q * inv_n - mean * mean;
    float sc = gamma[layer * EMB + c] * rsqrtf(var + 1e-5f);
    float sh = beta[layer * EMB + c] - mean * sc;
    g_stats[c]       = sc;
    g_stats[EMB + c] = sh;
}
__global__ void bn_apply_kernel(float* __restrict__ dst) {     // final layer
    int idx = blockIdx.x * blockDim.x + threadIdx.x;
    if (idx >= N_NODES * 75) return;
    int c = (idx % 75) * 4;
    float4 v = ((const float4*)g_agg)[idx];
    float4 r;
    r.x = v.x * g_stats[c + 0] + g_stats[EMB + c + 0];
    r.y = v.y * g_stats[c + 1] + g_stats[EMB + c + 1];
    r.z = v.z * g_stats[c + 2] + g_stats[EMB + c + 2];
    r.w = v.w * g_stats[c + 3] + g_stats[EMB + c + 3];
    ((float4*)dst)[idx] = r;
}

// ---------------------------------------------------------------------------
extern "C" void kernel_launch(void* const* d_in, const int* in_sizes, int n_in,
                              void* d_out, int out_size) {
    const int*   x     = (const int*)d_in[0];
    const int*   ei    = (const int*)d_in[1];
    const int*   ea    = (const int*)d_in[2];
    const float* xemb  = (const float*)d_in[3];
    const float* eemb  = (const float*)d_in[4];
    const float* W1    = (const float*)d_in[5];
    const float* b1    = (const float*)d_in[6];
    const float* W2    = (const float*)d_in[7];
    const float* b2    = (const float*)d_in[8];
    const float* gamma = (const float*)d_in[9];
    const float* beta  = (const float*)d_in[10];
    float* out = (float*)d_out;

    cudaFuncSetAttribute(gemm1_kernel,
                         cudaFuncAttributeMaxDynamicSharedMemorySize, GEMM_SMEM);
    cudaFuncSetAttribute(gemm2_kernel,
                         cudaFuncAttributeMaxDynamicSharedMemorySize, GEMM_SMEM);

    node_emb_kernel<<<(N_NODES * 75 + 255) / 256, 256>>>(x, xemb);       // #1
    prep_w1_kernel<<<(NLAYER * NP1 * KP1 + 255) / 256, 256>>>(W1);       // #2
    prep_w2_kernel<<<(NLAYER * NP2 * KP2 + 255) / 256, 256>>>(W2);       // #3

    // PROFILING PROBE at launch #4 (the one ncu captures): gather slice.
    // Output (g_aggh/g_aggl) fully overwritten by the real layer-0 gather.
    gather_kernel<<<98, 256>>>(eemb, 0);                                 // #4

    reset_kernel<<<(N_NODES + 255) / 256, 256>>>();
    hist_kernel<<<(N_EDGES + 255) / 256, 256>>>(ei, ea);
    scan1_kernel<<<NBLK256, 256>>>();
    scan2_kernel<<<1, 256>>>();
    scan3_kernel<<<NBLK256, 256>>>();
    fill_kernel<<<(N_EDGES + 255) / 256, 256>>>(ei);
    sort_kernel<<<(N_NODES + 255) / 256, 256>>>();

    const int ggrid = (N_NODES + 63) / 64;
    for (int layer = 0; layer < NLAYER; layer++) {
        gather_kernel<<<ggrid, 256>>>(eemb, layer);
        gemm1_kernel<<<dim3(M_PAD / 256, NP1 / 128), 512, GEMM_SMEM>>>(b1, layer);
        gemm2_kernel<<<dim3(M_PAD / 256, NP2 / 128), 512, GEMM_SMEM>>>(b2, layer);
        bn_final_kernel<<<1, 320>>>(gamma, beta, layer);
        if (layer < NLAYER - 1)
            bnrelu_kernel<<<(N_NODES * 75 + 255) / 256, 256>>>();
    }
    bn_apply_kernel<<<(N_NODES * 75 + 255) / 256, 256>>>(out);
}

// round 13
// speedup vs baseline: 1.1796x; 1.1796x over previous
#include <cuda_runtime.h>
#include <cuda_bf16.h>
#include <cstdint>

// ---------------------------------------------------------------------------
// GIN encoder, deterministic. GEMM1: 128x128 tile; GEMM2: 256x64 tile with
// fused BN partial stats (both 256 threads, 2 CTA/SM). mma.sync bf16 hi/lo
// (3-MMA), cp.async, ldmatrix. Gather: warp-per-node float4, BN pre-applied.
// ---------------------------------------------------------------------------
#define N_NODES 50000
#define M_PAD   50176           // 392*128 = 196*256
#define EMB     300
#define EMB2    600
#define N_EDGES 800000
#define NLAYER  5
#define NCHUNK  196             // BN row chunks of 256 (= GEMM2 M-tiles)
#define NBLK256 196

#define KP1 320
#define NP1 640
#define KP2 608
#define NP2 320

__device__ float g_h   [M_PAD * EMB];     // gather source (node emb / bn(h))
__device__ float g_agg [M_PAD * EMB];     // GEMM2 out / BN in
__device__ __align__(16) __nv_bfloat16 g_aggh[M_PAD * KP1];
__device__ __align__(16) __nv_bfloat16 g_aggl[M_PAD * KP1];
__device__ __align__(16) __nv_bfloat16 g_hidh[M_PAD * KP2];
__device__ __align__(16) __nv_bfloat16 g_hidl[M_PAD * KP2];
__device__ float g_stats[2 * EMB];
__device__ float g_part [NCHUNK * 2 * EMB];
__device__ int   g_deg [N_NODES];
__device__ int   g_cur [N_NODES];
__device__ int   g_cnt [N_NODES * 9];
__device__ int   g_off [N_NODES + 1];
__device__ int   g_src [N_EDGES];
__device__ int   g_bsum[256];
__device__ __align__(16) __nv_bfloat16 g_w1h[NLAYER * NP1 * KP1];
__device__ __align__(16) __nv_bfloat16 g_w1l[NLAYER * NP1 * KP1];
__device__ __align__(16) __nv_bfloat16 g_w2h[NLAYER * NP2 * KP2];
__device__ __align__(16) __nv_bfloat16 g_w2l[NLAYER * NP2 * KP2];

#define MMA16816(d, a, b0, b1)                                                \
    asm volatile("mma.sync.aligned.m16n8k16.row.col.f32.bf16.bf16.f32 "       \
        "{%0,%1,%2,%3}, {%4,%5,%6,%7}, {%8,%9}, {%0,%1,%2,%3};"               \
        : "+f"((d)[0]), "+f"((d)[1]), "+f"((d)[2]), "+f"((d)[3])              \
        : "r"((a)[0]), "r"((a)[1]), "r"((a)[2]), "r"((a)[3]),                 \
          "r"(b0), "r"(b1))

#define LDSM_X4(r, addr)                                                      \
    asm volatile("ldmatrix.sync.aligned.m8n8.x4.shared.b16 {%0,%1,%2,%3}, [%4];" \
        : "=r"((r)[0]), "=r"((r)[1]), "=r"((r)[2]), "=r"((r)[3]) : "r"(addr))

__device__ __forceinline__ void cpa16(uint32_t dst, const void* src) {
    asm volatile("cp.async.cg.shared.global [%0], [%1], 16;" :: "r"(dst), "l"(src));
}
#define CPA_COMMIT() asm volatile("cp.async.commit_group;" ::: "memory")
#define CPA_WAIT(n)  asm volatile("cp.async.wait_group %0;" :: "n"(n) : "memory")

__device__ __forceinline__ uint32_t smem_u32(const void* p) {
    uint32_t a;
    asm("{ .reg .u64 t; cvta.to.shared.u64 t, %1; cvt.u32.u64 %0, t; }" : "=r"(a) : "l"(p));
    return a;
}
__device__ __forceinline__ uint32_t packbf(float lo, float hi) {
    uint32_t r;
    asm("cvt.rn.bf16x2.f32 %0, %1, %2;" : "=r"(r) : "f"(hi), "f"(lo));
    return r;
}
__device__ __forceinline__ void split2(float x, float y, uint32_t& hi, uint32_t& lo) {
    __nv_bfloat16 hx = __float2bfloat16(x), hy = __float2bfloat16(y);
    hi = ((uint32_t)__bfloat16_as_ushort(hy) << 16) | __bfloat16_as_ushort(hx);
    lo = packbf(x - __bfloat162float(hx), y - __bfloat162float(hy));
}

// ---------------------------------------------------------------------------
__global__ void node_emb_kernel(const int* __restrict__ x,
                                const float* __restrict__ xemb) {
    int idx = blockIdx.x * blockDim.x + threadIdx.x;
    if (idx >= N_NODES * 75) return;
    int row = idx / 75;
    int c4  = idx - row * 75;
    int a = x[2 * row];
    int b = x[2 * row + 1];
    float4 va = ((const float4*)(xemb + a * EMB))[c4];
    float4 vb = ((const float4*)(xemb + b * EMB))[c4];
    va.x += vb.x; va.y += vb.y; va.z += vb.z; va.w += vb.w;
    ((float4*)g_h)[idx] = va;
}

// ---------------------------------------------------------------------------
__global__ void prep_w1_kernel(const float* __restrict__ W1) {
    int idx = blockIdx.x * blockDim.x + threadIdx.x;
    if (idx >= NLAYER * NP1 * KP1) return;
    int layer = idx / (NP1 * KP1);
    int rem = idx - layer * NP1 * KP1;
    int n = rem / KP1, k = rem - n * KP1;
    float v = (n < EMB2 && k < EMB) ? W1[layer * EMB * EMB2 + k * EMB2 + n] : 0.f;
    __nv_bfloat16 h = __float2bfloat16(v);
    g_w1h[idx] = h;
    g_w1l[idx] = __float2bfloat16(v - __bfloat162float(h));
}
__global__ void prep_w2_kernel(const float* __restrict__ W2) {
    int idx = blockIdx.x * blockDim.x + threadIdx.x;
    if (idx >= NLAYER * NP2 * KP2) return;
    int layer = idx / (NP2 * KP2);
    int rem = idx - layer * NP2 * KP2;
    int n = rem / KP2, k = rem - n * KP2;
    float v = (n < EMB && k < EMB2) ? W2[layer * EMB2 * EMB + k * EMB + n] : 0.f;
    __nv_bfloat16 h = __float2bfloat16(v);
    g_w2h[idx] = h;
    g_w2l[idx] = __float2bfloat16(v - __bfloat162float(h));
}

// ---------------------------------------------------------------------------
// CSR build (deterministic)
// ---------------------------------------------------------------------------
__global__ void reset_kernel() {
    int i = blockIdx.x * blockDim.x + threadIdx.x;
    if (i < N_NODES) {
        g_deg[i] = 0; g_cur[i] = 0;
        #pragma unroll
        for (int c = 0; c < 9; c++) g_cnt[i * 9 + c] = 0;
    }
}
__global__ void hist_kernel(const int* __restrict__ ei,
                            const int* __restrict__ ea) {
    int e = blockIdx.x * blockDim.x + threadIdx.x;
    if (e >= N_EDGES) return;
    int dst = ei[N_EDGES + e];
    int c = ea[2 * e] * 3 + ea[2 * e + 1];
    atomicAdd(&g_deg[dst], 1);
    atomicAdd(&g_cnt[dst * 9 + c], 1);
}
__global__ void scan1_kernel() {
    __shared__ int s[256];
    int tid = threadIdx.x;
    int i = blockIdx.x * 256 + tid;
    s[tid] = (i < N_NODES) ? g_deg[i] : 0;
    __syncthreads();
    #pragma unroll
    for (int d = 1; d < 256; d <<= 1) {
        int t = (tid >= d) ? s[tid - d] : 0;
        __syncthreads();
        s[tid] += t;
        __syncthreads();
    }
    if (i < N_NODES) g_off[i + 1] = s[tid];
    if (tid == 255) g_bsum[blockIdx.x] = s[255];
}
__global__ void scan2_kernel() {
    __shared__ int s[256];
    int tid = threadIdx.x;
    s[tid] = (tid < NBLK256) ? g_bsum[tid] : 0;
    __syncthreads();
    #pragma unroll
    for (int d = 1; d < 256; d <<= 1) {
        int t = (tid >= d) ? s[tid - d] : 0;
        __syncthreads();
        s[tid] += t;
        __syncthreads();
    }
    g_bsum[tid] = s[tid];
}
__global__ void scan3_kernel() {
    int i = blockIdx.x * 256 + threadIdx.x;
    if (i < N_NODES && blockIdx.x > 0) g_off[i + 1] += g_bsum[blockIdx.x - 1];
    if (i == 0) g_off[0] = 0;
}
__global__ void fill_kernel(const int* __restrict__ ei) {
    int e = blockIdx.x * blockDim.x + threadIdx.x;
    if (e >= N_EDGES) return;
    int dst = ei[N_EDGES + e];
    int slot = atomicAdd(&g_cur[dst], 1);
    g_src[g_off[dst] + slot] = ei[e];
}
__global__ void sort_kernel() {
    int n = blockIdx.x * blockDim.x + threadIdx.x;
    if (n >= N_NODES) return;
    int a = g_off[n], b = g_off[n + 1];
    for (int i = a + 1; i < b; i++) {
        int key = g_src[i];
        int j = i - 1;
        while (j >= a && g_src[j] > key) { g_src[j + 1] = g_src[j]; j--; }
        g_src[j + 1] = key;
    }
}

// ---------------------------------------------------------------------------
// Gather: warp-per-node, float4 (j = lane + k*32 < 75), 4-edge unroll,
// 4 nodes per warp (grid 1563). No intra-warp node divergence.
// agg[n] = g_h[n] + selfc + sum_c cnt[n][c]*comb[c] + sum_e g_h[src(e)]
// Deterministic: sorted edge order. Output bf16 hi/lo at stride KP1.
// ---------------------------------------------------------------------------
__global__ void __launch_bounds__(256) gather_kernel(const float* __restrict__ eemb,
                                                     int layer) {
    __shared__ __align__(16) float comb[9 * EMB];
    __shared__ __align__(16) float selfc[EMB];
    const float* emb = eemb + layer * 6 * EMB;
    for (int i = threadIdx.x; i < 9 * EMB; i += blockDim.x) {
        int c = i / EMB;
        int d = i - c * EMB;
        comb[i] = emb[(c / 3) * EMB + d] + emb[(c % 3) * EMB + d];
    }
    for (int i = threadIdx.x; i < EMB; i += blockDim.x)
        selfc[i] = emb[4 * EMB + i] + emb[0 * EMB + i];
    __syncthreads();

    int lane = threadIdx.x & 31;
    int wid  = threadIdx.x >> 5;
    const float4* comb4 = (const float4*)comb;
    const float4* sfc4  = (const float4*)selfc;

    for (int g = 0; g < 4; g++) {
        int node = (blockIdx.x * 8 + wid) * 4 + g;   // 32 nodes per block
        if (node >= N_NODES) break;                  // uniform per warp

        float4 acc[3];
        const float4* hn = (const float4*)(g_h + (size_t)node * EMB);
        #pragma unroll
        for (int k = 0; k < 3; k++) {
            int j = lane + k * 32;
            acc[k] = make_float4(0.f, 0.f, 0.f, 0.f);
            if (j < 75) {
                float4 a = hn[j], b = sfc4[j];
                acc[k].x = a.x + b.x; acc[k].y = a.y + b.y;
                acc[k].z = a.z + b.z; acc[k].w = a.w + b.w;
            }
        }
        const int* cnt = g_cnt + node * 9;
        #pragma unroll
        for (int cb = 0; cb < 9; cb++) {
            int cc = cnt[cb];
            if (cc) {
                float cf = (float)cc;
                #pragma unroll
                for (int k = 0; k < 3; k++) {
                    int j = lane + k * 32;
                    if (j < 75) {
                        float4 b = comb4[cb * 75 + j];
                        acc[k].x = fmaf(cf, b.x, acc[k].x);
                        acc[k].y = fmaf(cf, b.y, acc[k].y);
                        acc[k].z = fmaf(cf, b.z, acc[k].z);
                        acc[k].w = fmaf(cf, b.w, acc[k].w);
                    }
                }
            }
        }

        int beg = g_off[node], end = g_off[node + 1];
        int idx = beg;
        for (; idx + 3 < end; idx += 4) {
            int s0 = g_src[idx],     s1 = g_src[idx + 1];
            int s2 = g_src[idx + 2], s3 = g_src[idx + 3];
            const float4* h0 = (const float4*)(g_h + (size_t)s0 * EMB);
            const float4* h1 = (const float4*)(g_h + (size_t)s1 * EMB);
            const float4* h2 = (const float4*)(g_h + (size_t)s2 * EMB);
            const float4* h3 = (const float4*)(g_h + (size_t)s3 * EMB);
            #pragma unroll
            for (int k = 0; k < 3; k++) {
                int j = lane + k * 32;
                if (j < 75) {
                    float4 a = h0[j], b = h1[j], c = h2[j], d = h3[j];
                    acc[k].x += (a.x + b.x) + (c.x + d.x);
                    acc[k].y += (a.y + b.y) + (c.y + d.y);
                    acc[k].z += (a.z + b.z) + (c.z + d.z);
                    acc[k].w += (a.w + b.w) + (c.w + d.w);
                }
            }
        }
        for (; idx < end; idx++) {
            int s0 = g_src[idx];
            const float4* h0 = (const float4*)(g_h + (size_t)s0 * EMB);
            #pragma unroll
            for (int k = 0; k < 3; k++) {
                int j = lane + k * 32;
                if (j < 75) {
                    float4 a = h0[j];
                    acc[k].x += a.x; acc[k].y += a.y;
                    acc[k].z += a.z; acc[k].w += a.w;
                }
            }
        }

        #pragma unroll
        for (int k = 0; k < 3; k++) {
            int j = lane + k * 32;
            if (j < 75) {
                uint32_t h01, l01, h23, l23;
                split2(acc[k].x, acc[k].y, h01, l01);
                split2(acc[k].z, acc[k].w, h23, l23);
                uint2 hv; hv.x = h01; hv.y = h23;
                uint2 lv; lv.x = l01; lv.y = l23;
                *(uint2*)(g_aggh + (size_t)node * KP1 + j * 4) = hv;
                *(uint2*)(g_aggl + (size_t)node * KP1 + j * 4) = lv;
            }
        }
    }
}

// ---------------------------------------------------------------------------
// bnrelu: g_h = relu(bn(g_agg)) once per layer.
// ---------------------------------------------------------------------------
__global__ void bnrelu_kernel() {
    int idx = blockIdx.x * blockDim.x + threadIdx.x;
    if (idx >= N_NODES * 75) return;
    int c = (idx % 75) * 4;
    float4 v = ((const float4*)g_agg)[idx];
    float4 r;
    r.x = fmaxf(fmaf(v.x, g_stats[c + 0], g_stats[EMB + c + 0]), 0.f);
    r.y = fmaxf(fmaf(v.y, g_stats[c + 1], g_stats[EMB + c + 1]), 0.f);
    r.z = fmaxf(fmaf(v.z, g_stats[c + 2], g_stats[EMB + c + 2]), 0.f);
    r.w = fmaxf(fmaf(v.w, g_stats[c + 3], g_stats[EMB + c + 3]), 0.f);
    ((float4*)g_h)[idx] = r;
}

// ---------------------------------------------------------------------------
// GEMM1: 128x128 tile, 256 threads, 8 warps (4Mx2N, warp 32x64), relu,
// bf16 hi/lo out. cp.async double buffer, single sync per chunk, ldmatrix.
// ---------------------------------------------------------------------------
#define STG_BYTES 40960
#define OFF_AH 0
#define OFF_AL 10240
#define OFF_BH 20480
#define OFF_BL 30720
#define GEMM1_SMEM (2 * STG_BYTES)

__global__ void __launch_bounds__(256, 2) gemm1_kernel(const float* __restrict__ ball,
                                                       int layer) {
    constexpr int NDIM = EMB2, KPAD = KP1, NPAD = NP1, NKB = KP1 / 32;

    extern __shared__ __align__(16) char sm[];
    uint32_t sb = smem_u32(sm);

    int tid  = threadIdx.x;
    int lane = tid & 31;
    int wid  = tid >> 5;
    int wm   = (wid & 3) * 32;
    int wn   = (wid >> 2) * 64;
    int m0   = blockIdx.x * 128;
    int n0   = blockIdx.y * 128;

    int lg = lane >> 3, lj = lane & 7;
    int a_row = (lg & 1) * 8 + lj;
    int a_k8  = (lg >> 1) * 8;
    int b_row = (lg >> 1) * 8 + lj;
    int b_k8  = (lg & 1) * 8;

    float acc[2][8][4];
    #pragma unroll
    for (int mt = 0; mt < 2; mt++)
        #pragma unroll
        for (int nt = 0; nt < 8; nt++)
            #pragma unroll
            for (int q = 0; q < 4; q++) acc[mt][nt][q] = 0.f;

    const size_t bbase = ((size_t)layer * NPAD + n0) * KPAD;

    auto issue = [&](int kb, int st) {
        uint32_t base = sb + st * STG_BYTES;
        #pragma unroll
        for (int i = 0; i < 2; i++) {
            int v = tid + i * 256;
            int r = v >> 2;
            int c = v & 3;
            uint32_t so = r * 80 + c * 16;
            size_t ga = (size_t)(m0 + r) * KPAD + kb * 32 + c * 8;
            cpa16(base + OFF_AH + so, g_aggh + ga);
            cpa16(base + OFF_AL + so, g_aggl + ga);
            size_t gb = bbase + (size_t)r * KPAD + kb * 32 + c * 8;
            cpa16(base + OFF_BH + so, g_w1h + gb);
            cpa16(base + OFF_BL + so, g_w1l + gb);
        }
        CPA_COMMIT();
    };

    issue(0, 0);

    for (int kb = 0; kb < NKB; kb++) {
        int st = kb & 1;
        CPA_WAIT(0);
        __syncthreads();
        if (kb + 1 < NKB) issue(kb + 1, st ^ 1);

        uint32_t stbase = sb + st * STG_BYTES;
        #pragma unroll
        for (int c = 0; c < 2; c++) {
            uint32_t akoff = (uint32_t)(c * 16 + a_k8) * 2;
            uint32_t bkoff = (uint32_t)(c * 16 + b_k8) * 2;
            uint32_t ah[2][4], al[2][4];
            #pragma unroll
            for (int mt = 0; mt < 2; mt++) {
                uint32_t ra = stbase + (uint32_t)(wm + mt * 16 + a_row) * 80 + akoff;
                LDSM_X4(ah[mt], ra + OFF_AH);
                LDSM_X4(al[mt], ra + OFF_AL);
            }
            #pragma unroll
            for (int ntp = 0; ntp < 4; ntp++) {
                uint32_t rb = stbase + (uint32_t)(wn + ntp * 16 + b_row) * 80 + bkoff;
                uint32_t bh[4], bl[4];
                LDSM_X4(bh, rb + OFF_BH);
                LDSM_X4(bl, rb + OFF_BL);
                #pragma unroll
                for (int sub = 0; sub < 2; sub++) {
                    #pragma unroll
                    for (int mt = 0; mt < 2; mt++) {
                        float* d = acc[mt][ntp * 2 + sub];
                        MMA16816(d, ah[mt], bh[sub * 2], bh[sub * 2 + 1]);
                        MMA16816(d, ah[mt], bl[sub * 2], bl[sub * 2 + 1]);
                        MMA16816(d, al[mt], bh[sub * 2], bh[sub * 2 + 1]);
                    }
                }
            }
        }
    }

    const float* bias = ball + layer * NDIM;
    #pragma unroll
    for (int mt = 0; mt < 2; mt++) {
        #pragma unroll
        for (int hrow = 0; hrow < 2; hrow++) {
            int row = m0 + wm + mt * 16 + (lane >> 2) + hrow * 8;
            #pragma unroll
            for (int nt = 0; nt < 8; nt++) {
                int col = n0 + wn + nt * 8 + (lane & 3) * 2;
                if (col < NDIM) {
                    float v0 = fmaxf(acc[mt][nt][hrow * 2 + 0] + __ldg(bias + col), 0.f);
                    float v1 = fmaxf(acc[mt][nt][hrow * 2 + 1] + __ldg(bias + col + 1), 0.f);
                    uint32_t hi, lo;
                    split2(v0, v1, hi, lo);
                    *(uint32_t*)(g_hidh + (size_t)row * KP2 + col) = hi;
                    *(uint32_t*)(g_hidl + (size_t)row * KP2 + col) = lo;
                }
            }
        }
    }
}

// ---------------------------------------------------------------------------
// GEMM2: 256x64 tile, 256 threads, 8 M-warps (warp 32x64), fp32 out + fused
// BN partials.
// ---------------------------------------------------------------------------
#define STG2_BYTES 51200
#define OFF2_AH 0
#define OFF2_AL 20480
#define OFF2_BH 40960
#define OFF2_BL 46080
#define GEMM2_SMEM (2 * STG2_BYTES)

__global__ void __launch_bounds__(256, 2) gemm2_kernel(const float* __restrict__ ball,
                                                       int layer) {
    constexpr int NDIM = EMB, KPAD = KP2, NPAD = NP2, NKB = KP2 / 32;

    extern __shared__ __align__(16) char sm[];
    uint32_t sb = smem_u32(sm);

    int tid  = threadIdx.x;
    int lane = tid & 31;
    int wid  = tid >> 5;
    int wm   = wid * 32;
    int m0   = blockIdx.x * 256;
    int n0   = blockIdx.y * 64;

    int lg = lane >> 3, lj = lane & 7;
    int a_row = (lg & 1) * 8 + lj;
    int a_k8  = (lg >> 1) * 8;
    int b_row = (lg >> 1) * 8 + lj;
    int b_k8  = (lg & 1) * 8;

    float acc[2][8][4];
    #pragma unroll
    for (int mt = 0; mt < 2; mt++)
        #pragma unroll
        for (int nt = 0; nt < 8; nt++)
            #pragma unroll
            for (int q = 0; q < 4; q++) acc[mt][nt][q] = 0.f;

    const size_t bbase = ((size_t)layer * NPAD + n0) * KPAD;

    auto issue = [&](int kb, int st) {
        uint32_t base = sb + st * STG2_BYTES;
        #pragma unroll
        for (int i = 0; i < 10; i++) {
            int v = tid + i * 256;
            if (v < 2048) {
                int arr = v >> 10;
                int rem = v & 1023;
                int r = rem >> 2, c = rem & 3;
                uint32_t so = (arr ? OFF2_AL : OFF2_AH) + r * 80 + c * 16;
                size_t ga = (size_t)(m0 + r) * KPAD + kb * 32 + c * 8;
                cpa16(base + so, (arr ? g_hidl : g_hidh) + ga);
            } else {
                int v2 = v - 2048;
                int arr = v2 >> 8;
                int rem = v2 & 255;
                int r = rem >> 2, c = rem & 3;
                uint32_t so = (arr ? OFF2_BL : OFF2_BH) + r * 80 + c * 16;
                size_t gb = bbase + (size_t)r * KPAD + kb * 32 + c * 8;
                cpa16(base + so, (arr ? g_w2l : g_w2h) + gb);
            }
        }
        CPA_COMMIT();
    };

    issue(0, 0);

    for (int kb = 0; kb < NKB; kb++) {
        int st = kb & 1;
        CPA_WAIT(0);
        __syncthreads();
        if (kb + 1 < NKB) issue(kb + 1, st ^ 1);

        uint32_t stbase = sb + st * STG2_BYTES;
        #pragma unroll
        for (int c = 0; c < 2; c++) {
            uint32_t akoff = (uint32_t)(c * 16 + a_k8) * 2;
            uint32_t bkoff = (uint32_t)(c * 16 + b_k8) * 2;
            uint32_t ah[2][4], al[2][4];
            #pragma unroll
            for (int mt = 0; mt < 2; mt++) {
                uint32_t ra = stbase + (uint32_t)(wm + mt * 16 + a_row) * 80 + akoff;
                LDSM_X4(ah[mt], ra + OFF2_AH);
                LDSM_X4(al[mt], ra + OFF2_AL);
            }
            #pragma unroll
            for (int ntp = 0; ntp < 4; ntp++) {
                uint32_t rb = stbase + (uint32_t)(ntp * 16 + b_row) * 80 + bkoff;
                uint32_t bh[4], bl[4];
                LDSM_X4(bh, rb + OFF2_BH);
                LDSM_X4(bl, rb + OFF2_BL);
                #pragma unroll
                for (int sub = 0; sub < 2; sub++) {
                    #pragma unroll
                    for (int mt = 0; mt < 2; mt++) {
                        float* d = acc[mt][ntp * 2 + sub];
                        MMA16816(d, ah[mt], bh[sub * 2], bh[sub * 2 + 1]);
                        MMA16816(d, ah[mt], bl[sub * 2], bl[sub * 2 + 1]);
                        MMA16816(d, al[mt], bh[sub * 2], bh[sub * 2 + 1]);
                    }
                }
            }
        }
    }

    // --- epilogue: fp32 store + fused BN partials (rows < N_NODES) ---
    __syncthreads();                    // stages dead; reuse smem for reduce
    float* red = (float*)sm;            // [8 warps][8 nt][4 L][4 vals] = 4KB
    const float* bias = ball + layer * NDIM;

    #pragma unroll
    for (int nt = 0; nt < 8; nt++) {
        int col = n0 + nt * 8 + (lane & 3) * 2;
        float bv0 = (col     < NDIM) ? __ldg(bias + col)     : 0.f;
        float bv1 = (col + 1 < NDIM) ? __ldg(bias + col + 1) : 0.f;
        float s0 = 0.f, q0 = 0.f, s1 = 0.f, q1 = 0.f;
        #pragma unroll
        for (int mt = 0; mt < 2; mt++) {
            #pragma unroll
            for (int hrow = 0; hrow < 2; hrow++) {
                int row = m0 + wm + mt * 16 + (lane >> 2) + hrow * 8;
                float v0 = acc[mt][nt][hrow * 2 + 0] + bv0;
                float v1 = acc[mt][nt][hrow * 2 + 1] + bv1;
                if (col < NDIM) {
                    float2 stv; stv.x = v0; stv.y = v1;
                    *(float2*)(g_agg + (size_t)row * EMB + col) = stv;
                }
                if (row < N_NODES) {
                    s0 += v0; q0 += v0 * v0;
                    s1 += v1; q1 += v1 * v1;
                }
            }
        }
        #pragma unroll
        for (int d = 4; d < 32; d <<= 1) {
            s0 += __shfl_xor_sync(0xffffffffu, s0, d);
            q0 += __shfl_xor_sync(0xffffffffu, q0, d);
            s1 += __shfl_xor_sync(0xffffffffu, s1, d);
            q1 += __shfl_xor_sync(0xffffffffu, q1, d);
        }
        if (lane < 4) {
            float* p = red + ((wid * 8 + nt) * 4 + lane) * 4;
            p[0] = s0; p[1] = q0; p[2] = s1; p[3] = q1;
        }
    }
    __syncthreads();
    if (tid < 32) {
        int nt = tid >> 2, L = tid & 3;
        float s0 = 0.f, q0 = 0.f, s1 = 0.f, q1 = 0.f;
        #pragma unroll
        for (int w = 0; w < 8; w++) {
            const float* p = red + ((w * 8 + nt) * 4 + L) * 4;
            s0 += p[0]; q0 += p[1]; s1 += p[2]; q1 += p[3];
        }
        int col = n0 + nt * 8 + L * 2;
        int bx = blockIdx.x;
        if (col < NDIM) {
            g_part[bx * 2 * EMB + col]       = s0;
            g_part[bx * 2 * EMB + EMB + col] = q0;
        }
        if (col + 1 < NDIM) {
            g_part[bx * 2 * EMB + col + 1]       = s1;
            g_part[bx * 2 * EMB + EMB + col + 1] = q1;
        }
    }
}

// ---------------------------------------------------------------------------
__global__ void bn_final_kernel(const float* __restrict__ gamma,
                                const float* __restrict__ beta, int layer) {
    int c = threadIdx.x;
    if (c >= EMB) return;
    float s = 0.f, q = 0.f;
    for (int b = 0; b < NCHUNK; b++) {
        s += g_part[b * 2 * EMB + c];
        q += g_part[b * 2 * EMB + EMB + c];
    }
    const float inv_n = 1.0f / (float)N_NODES;
    float mean = s * inv_n;
    float var  = q * inv_n - mean * mean;
    float sc = gamma[layer * EMB + c] * rsqrtf(var + 1e-5f);
    float sh = beta[layer * EMB + c] - mean * sc;
    g_stats[c]       = sc;
    g_stats[EMB + c] = sh;
}
__global__ void bn_apply_kernel(float* __restrict__ dst) {     // final layer
    int idx = blockIdx.x * blockDim.x + threadIdx.x;
    if (idx >= N_NODES * 75) return;
    int c = (idx % 75) * 4;
    float4 v = ((const float4*)g_agg)[idx];
    float4 r;
    r.x = v.x * g_stats[c + 0] + g_stats[EMB + c + 0];
    r.y = v.y * g_stats[c + 1] + g_stats[EMB + c + 1];
    r.z = v.z * g_stats[c + 2] + g_stats[EMB + c + 2];
    r.w = v.w * g_stats[c + 3] + g_stats[EMB + c + 3];
    ((float4*)dst)[idx] = r;
}

// ---------------------------------------------------------------------------
extern "C" void kernel_launch(void* const* d_in, const int* in_sizes, int n_in,
                              void* d_out, int out_size) {
    const int*   x     = (const int*)d_in[0];
    const int*   ei    = (const int*)d_in[1];
    const int*   ea    = (const int*)d_in[2];
    const float* xemb  = (const float*)d_in[3];
    const float* eemb  = (const float*)d_in[4];
    const float* W1    = (const float*)d_in[5];
    const float* b1    = (const float*)d_in[6];
    const float* W2    = (const float*)d_in[7];
    const float* b2    = (const float*)d_in[8];
    const float* gamma = (const float*)d_in[9];
    const float* beta  = (const float*)d_in[10];
    float* out = (float*)d_out;

    cudaFuncSetAttribute(gemm1_kernel,
                         cudaFuncAttributeMaxDynamicSharedMemorySize, GEMM1_SMEM);
    cudaFuncSetAttribute(gemm2_kernel,
                         cudaFuncAttributeMaxDynamicSharedMemorySize, GEMM2_SMEM);

    node_emb_kernel<<<(N_NODES * 75 + 255) / 256, 256>>>(x, xemb);
    prep_w1_kernel<<<(NLAYER * NP1 * KP1 + 255) / 256, 256>>>(W1);
    prep_w2_kernel<<<(NLAYER * NP2 * KP2 + 255) / 256, 256>>>(W2);

    reset_kernel<<<(N_NODES + 255) / 256, 256>>>();
    hist_kernel<<<(N_EDGES + 255) / 256, 256>>>(ei, ea);
    scan1_kernel<<<NBLK256, 256>>>();
    scan2_kernel<<<1, 256>>>();
    scan3_kernel<<<NBLK256, 256>>>();
    fill_kernel<<<(N_EDGES + 255) / 256, 256>>>(ei);
    sort_kernel<<<(N_NODES + 255) / 256, 256>>>();

    const int ggrid = (N_NODES + 31) / 32;   // 32 nodes per block
    for (int layer = 0; layer < NLAYER; layer++) {
        gather_kernel<<<ggrid, 256>>>(eemb, layer);
        gemm1_kernel<<<dim3(M_PAD / 128, NP1 / 128), 256, GEMM1_SMEM>>>(b1, layer);
        gemm2_kernel<<<dim3(M_PAD / 256, NP2 / 64), 256, GEMM2_SMEM>>>(b2, layer);
        bn_final_kernel<<<1, 320>>>(gamma, beta, layer);
        if (layer < NLAYER - 1)
            bnrelu_kernel<<<(N_NODES * 75 + 255) / 256, 256>>>();
    }
    bn_apply_kernel<<<(N_NODES * 75 + 255) / 256, 256>>>(out);
}

// round 14
// speedup vs baseline: 1.2267x; 1.0400x over previous
#include <cuda_runtime.h>
#include <cuda_bf16.h>
#include <cstdint>

// ---------------------------------------------------------------------------
// GIN encoder, deterministic. GEMM1: 128x128 tile; GEMM2: 256x64 tile with
// fused BN partial stats. mma.sync bf16 hi/lo (3-MMA), cp.async, ldmatrix.
// Gather: column-parallel 160-thread, BN fused. (R9 best config + fast
// parallel bn_final.)
// ---------------------------------------------------------------------------
#define N_NODES 50000
#define M_PAD   50176           // 392*128 = 196*256
#define EMB     300
#define EMB2    600
#define N_EDGES 800000
#define NLAYER  5
#define NCHUNK  196             // BN row chunks of 256 (= GEMM2 M-tiles)
#define NBLK256 196
#define GNODES  16

#define KP1 320
#define NP1 640
#define KP2 608
#define NP2 320

__device__ float g_h   [M_PAD * EMB];
__device__ float g_agg [M_PAD * EMB];
__device__ __align__(16) __nv_bfloat16 g_aggh[M_PAD * KP1];
__device__ __align__(16) __nv_bfloat16 g_aggl[M_PAD * KP1];
__device__ __align__(16) __nv_bfloat16 g_hidh[M_PAD * KP2];
__device__ __align__(16) __nv_bfloat16 g_hidl[M_PAD * KP2];
__device__ float g_stats[2 * EMB];
__device__ float g_part [NCHUNK * 2 * EMB];
__device__ int   g_deg [N_NODES];
__device__ int   g_cur [N_NODES];
__device__ int   g_cnt [N_NODES * 9];
__device__ int   g_off [N_NODES + 1];
__device__ int   g_src [N_EDGES];
__device__ int   g_bsum[256];
__device__ __align__(16) __nv_bfloat16 g_w1h[NLAYER * NP1 * KP1];
__device__ __align__(16) __nv_bfloat16 g_w1l[NLAYER * NP1 * KP1];
__device__ __align__(16) __nv_bfloat16 g_w2h[NLAYER * NP2 * KP2];
__device__ __align__(16) __nv_bfloat16 g_w2l[NLAYER * NP2 * KP2];

#define MMA16816(d, a, b0, b1)                                                \
    asm volatile("mma.sync.aligned.m16n8k16.row.col.f32.bf16.bf16.f32 "       \
        "{%0,%1,%2,%3}, {%4,%5,%6,%7}, {%8,%9}, {%0,%1,%2,%3};"               \
        : "+f"((d)[0]), "+f"((d)[1]), "+f"((d)[2]), "+f"((d)[3])              \
        : "r"((a)[0]), "r"((a)[1]), "r"((a)[2]), "r"((a)[3]),                 \
          "r"(b0), "r"(b1))

#define LDSM_X4(r, addr)                                                      \
    asm volatile("ldmatrix.sync.aligned.m8n8.x4.shared.b16 {%0,%1,%2,%3}, [%4];" \
        : "=r"((r)[0]), "=r"((r)[1]), "=r"((r)[2]), "=r"((r)[3]) : "r"(addr))

__device__ __forceinline__ void cpa16(uint32_t dst, const void* src) {
    asm volatile("cp.async.cg.shared.global [%0], [%1], 16;" :: "r"(dst), "l"(src));
}
#define CPA_COMMIT() asm volatile("cp.async.commit_group;" ::: "memory")
#define CPA_WAIT(n)  asm volatile("cp.async.wait_group %0;" :: "n"(n) : "memory")

__device__ __forceinline__ uint32_t smem_u32(const void* p) {
    uint32_t a;
    asm("{ .reg .u64 t; cvta.to.shared.u64 t, %1; cvt.u32.u64 %0, t; }" : "=r"(a) : "l"(p));
    return a;
}
__device__ __forceinline__ uint32_t packbf(float lo, float hi) {
    uint32_t r;
    asm("cvt.rn.bf16x2.f32 %0, %1, %2;" : "=r"(r) : "f"(hi), "f"(lo));
    return r;
}
__device__ __forceinline__ void split2(float x, float y, uint32_t& hi, uint32_t& lo) {
    __nv_bfloat16 hx = __float2bfloat16(x), hy = __float2bfloat16(y);
    hi = ((uint32_t)__bfloat16_as_ushort(hy) << 16) | __bfloat16_as_ushort(hx);
    lo = packbf(x - __bfloat162float(hx), y - __bfloat162float(hy));
}

// ---------------------------------------------------------------------------
__global__ void node_emb_kernel(const int* __restrict__ x,
                                const float* __restrict__ xemb) {
    int idx = blockIdx.x * blockDim.x + threadIdx.x;
    if (idx >= N_NODES * 75) return;
    int row = idx / 75;
    int c4  = idx - row * 75;
    int a = x[2 * row];
    int b = x[2 * row + 1];
    float4 va = ((const float4*)(xemb + a * EMB))[c4];
    float4 vb = ((const float4*)(xemb + b * EMB))[c4];
    va.x += vb.x; va.y += vb.y; va.z += vb.z; va.w += vb.w;
    ((float4*)g_h)[idx] = va;
}

// ---------------------------------------------------------------------------
__global__ void prep_w1_kernel(const float* __restrict__ W1) {
    int idx = blockIdx.x * blockDim.x + threadIdx.x;
    if (idx >= NLAYER * NP1 * KP1) return;
    int layer = idx / (NP1 * KP1);
    int rem = idx - layer * NP1 * KP1;
    int n = rem / KP1, k = rem - n * KP1;
    float v = (n < EMB2 && k < EMB) ? W1[layer * EMB * EMB2 + k * EMB2 + n] : 0.f;
    __nv_bfloat16 h = __float2bfloat16(v);
    g_w1h[idx] = h;
    g_w1l[idx] = __float2bfloat16(v - __bfloat162float(h));
}
__global__ void prep_w2_kernel(const float* __restrict__ W2) {
    int idx = blockIdx.x * blockDim.x + threadIdx.x;
    if (idx >= NLAYER * NP2 * KP2) return;
    int layer = idx / (NP2 * KP2);
    int rem = idx - layer * NP2 * KP2;
    int n = rem / KP2, k = rem - n * KP2;
    float v = (n < EMB && k < EMB2) ? W2[layer * EMB2 * EMB + k * EMB + n] : 0.f;
    __nv_bfloat16 h = __float2bfloat16(v);
    g_w2h[idx] = h;
    g_w2l[idx] = __float2bfloat16(v - __bfloat162float(h));
}

// ---------------------------------------------------------------------------
// CSR build (deterministic)
// ---------------------------------------------------------------------------
__global__ void reset_kernel() {
    int i = blockIdx.x * blockDim.x + threadIdx.x;
    if (i < N_NODES) {
        g_deg[i] = 0; g_cur[i] = 0;
        #pragma unroll
        for (int c = 0; c < 9; c++) g_cnt[i * 9 + c] = 0;
    }
}
__global__ void hist_kernel(const int* __restrict__ ei,
                            const int* __restrict__ ea) {
    int e = blockIdx.x * blockDim.x + threadIdx.x;
    if (e >= N_EDGES) return;
    int dst = ei[N_EDGES + e];
    int c = ea[2 * e] * 3 + ea[2 * e + 1];
    atomicAdd(&g_deg[dst], 1);
    atomicAdd(&g_cnt[dst * 9 + c], 1);
}
__global__ void scan1_kernel() {
    __shared__ int s[256];
    int tid = threadIdx.x;
    int i = blockIdx.x * 256 + tid;
    s[tid] = (i < N_NODES) ? g_deg[i] : 0;
    __syncthreads();
    #pragma unroll
    for (int d = 1; d < 256; d <<= 1) {
        int t = (tid >= d) ? s[tid - d] : 0;
        __syncthreads();
        s[tid] += t;
        __syncthreads();
    }
    if (i < N_NODES) g_off[i + 1] = s[tid];
    if (tid == 255) g_bsum[blockIdx.x] = s[255];
}
__global__ void scan2_kernel() {
    __shared__ int s[256];
    int tid = threadIdx.x;
    s[tid] = (tid < NBLK256) ? g_bsum[tid] : 0;
    __syncthreads();
    #pragma unroll
    for (int d = 1; d < 256; d <<= 1) {
        int t = (tid >= d) ? s[tid - d] : 0;
        __syncthreads();
        s[tid] += t;
        __syncthreads();
    }
    g_bsum[tid] = s[tid];
}
__global__ void scan3_kernel() {
    int i = blockIdx.x * 256 + threadIdx.x;
    if (i < N_NODES && blockIdx.x > 0) g_off[i + 1] += g_bsum[blockIdx.x - 1];
    if (i == 0) g_off[0] = 0;
}
__global__ void fill_kernel(const int* __restrict__ ei) {
    int e = blockIdx.x * blockDim.x + threadIdx.x;
    if (e >= N_EDGES) return;
    int dst = ei[N_EDGES + e];
    int slot = atomicAdd(&g_cur[dst], 1);
    g_src[g_off[dst] + slot] = ei[e];
}
__global__ void sort_kernel() {          // sort src values; equal keys commute
    int n = blockIdx.x * blockDim.x + threadIdx.x;
    if (n >= N_NODES) return;
    int a = g_off[n], b = g_off[n + 1];
    for (int i = a + 1; i < b; i++) {
        int key = g_src[i];
        int j = i - 1;
        while (j >= a && g_src[j] > key) { g_src[j + 1] = g_src[j]; j--; }
        g_src[j + 1] = key;
    }
}

// ---------------------------------------------------------------------------
// Gather, column-parallel (BN fused when BN=true). Deterministic.
// ---------------------------------------------------------------------------
template <bool BN>
__global__ void __launch_bounds__(160) gather_kernel(const float* __restrict__ srcdata,
                                                     const float* __restrict__ eemb,
                                                     int layer) {
    __shared__ __align__(16) float comb[9 * EMB];
    __shared__ __align__(16) float selfc[EMB];
    __shared__ __align__(16) float scs[EMB];
    __shared__ __align__(16) float shs[EMB];
    const float* emb = eemb + layer * 6 * EMB;
    for (int i = threadIdx.x; i < 9 * EMB; i += blockDim.x) {
        int c = i / EMB;
        int d = i - c * EMB;
        comb[i] = emb[(c / 3) * EMB + d] + emb[(c % 3) * EMB + d];
    }
    for (int i = threadIdx.x; i < EMB; i += blockDim.x) {
        selfc[i] = emb[4 * EMB + i] + emb[0 * EMB + i];
        if (BN) { scs[i] = g_stats[i]; shs[i] = g_stats[EMB + i]; }
    }
    __syncthreads();
    int t = threadIdx.x;
    if (t >= 150) return;
    int col = 2 * t;

    float2 scv, shv;
    if (BN) { scv = *(const float2*)&scs[col]; shv = *(const float2*)&shs[col]; }
    float2 sfc = *(const float2*)&selfc[col];

    int nodebase = blockIdx.x * GNODES;
    for (int g = 0; g < GNODES; g++) {
        int node = nodebase + g;
        if (node >= N_NODES) break;

        float2 v = *(const float2*)(srcdata + (size_t)node * EMB + col);
        if (BN) {
            v.x = fmaxf(fmaf(v.x, scv.x, shv.x), 0.f);
            v.y = fmaxf(fmaf(v.y, scv.y, shv.y), 0.f);
        }
        float2 acc;
        acc.x = v.x + sfc.x;
        acc.y = v.y + sfc.y;

        const int* cnt = g_cnt + node * 9;
        #pragma unroll
        for (int cb = 0; cb < 9; cb++) {
            int cc = cnt[cb];
            if (cc) {
                float cf = (float)cc;
                float2 b = *(const float2*)&comb[cb * EMB + col];
                acc.x = fmaf(cf, b.x, acc.x);
                acc.y = fmaf(cf, b.y, acc.y);
            }
        }

        int beg = g_off[node], end = g_off[node + 1];
        int idx = beg;
        for (; idx + 1 < end; idx += 2) {
            int s0 = g_src[idx], s1 = g_src[idx + 1];
            float2 a = *(const float2*)(srcdata + (size_t)s0 * EMB + col);
            float2 b = *(const float2*)(srcdata + (size_t)s1 * EMB + col);
            if (BN) {
                a.x = fmaxf(fmaf(a.x, scv.x, shv.x), 0.f);
                a.y = fmaxf(fmaf(a.y, scv.y, shv.y), 0.f);
                b.x = fmaxf(fmaf(b.x, scv.x, shv.x), 0.f);
                b.y = fmaxf(fmaf(b.y, scv.y, shv.y), 0.f);
            }
            acc.x += a.x + b.x;
            acc.y += a.y + b.y;
        }
        if (idx < end) {
            int s0 = g_src[idx];
            float2 a = *(const float2*)(srcdata + (size_t)s0 * EMB + col);
            if (BN) {
                a.x = fmaxf(fmaf(a.x, scv.x, shv.x), 0.f);
                a.y = fmaxf(fmaf(a.y, scv.y, shv.y), 0.f);
            }
            acc.x += a.x;
            acc.y += a.y;
        }

        uint32_t hi, lo;
        split2(acc.x, acc.y, hi, lo);
        *(uint32_t*)(g_aggh + (size_t)node * KP1 + col) = hi;
        *(uint32_t*)(g_aggl + (size_t)node * KP1 + col) = lo;
    }
}

// ---------------------------------------------------------------------------
// GEMM1: 128x128 tile, 256 threads, 8 warps (4Mx2N), relu, bf16 hi/lo out.
// ---------------------------------------------------------------------------
#define STG_BYTES 40960
#define OFF_AH 0
#define OFF_AL 10240
#define OFF_BH 20480
#define OFF_BL 30720
#define GEMM1_SMEM (2 * STG_BYTES)

__global__ void __launch_bounds__(256, 2) gemm1_kernel(const float* __restrict__ ball,
                                                       int layer) {
    constexpr int NDIM = EMB2, KPAD = KP1, NPAD = NP1, NKB = KP1 / 32;

    extern __shared__ __align__(16) char sm[];
    uint32_t sb = smem_u32(sm);

    int tid  = threadIdx.x;
    int lane = tid & 31;
    int wid  = tid >> 5;
    int wm   = (wid & 3) * 32;
    int wn   = (wid >> 2) * 64;
    int m0   = blockIdx.x * 128;
    int n0   = blockIdx.y * 128;

    int lg = lane >> 3, lj = lane & 7;
    int a_row = (lg & 1) * 8 + lj;
    int a_k8  = (lg >> 1) * 8;
    int b_row = (lg >> 1) * 8 + lj;
    int b_k8  = (lg & 1) * 8;

    float acc[2][8][4];
    #pragma unroll
    for (int mt = 0; mt < 2; mt++)
        #pragma unroll
        for (int nt = 0; nt < 8; nt++)
            #pragma unroll
            for (int q = 0; q < 4; q++) acc[mt][nt][q] = 0.f;

    const size_t bbase = ((size_t)layer * NPAD + n0) * KPAD;

    auto issue = [&](int kb, int st) {
        uint32_t base = sb + st * STG_BYTES;
        #pragma unroll
        for (int i = 0; i < 2; i++) {
            int v = tid + i * 256;
            int r = v >> 2;
            int c = v & 3;
            uint32_t so = r * 80 + c * 16;
            size_t ga = (size_t)(m0 + r) * KPAD + kb * 32 + c * 8;
            cpa16(base + OFF_AH + so, g_aggh + ga);
            cpa16(base + OFF_AL + so, g_aggl + ga);
            size_t gb = bbase + (size_t)r * KPAD + kb * 32 + c * 8;
            cpa16(base + OFF_BH + so, g_w1h + gb);
            cpa16(base + OFF_BL + so, g_w1l + gb);
        }
        CPA_COMMIT();
    };

    issue(0, 0);

    for (int kb = 0; kb < NKB; kb++) {
        int st = kb & 1;
        CPA_WAIT(0);
        __syncthreads();
        if (kb + 1 < NKB) issue(kb + 1, st ^ 1);

        uint32_t stbase = sb + st * STG_BYTES;
        #pragma unroll
        for (int c = 0; c < 2; c++) {
            uint32_t akoff = (uint32_t)(c * 16 + a_k8) * 2;
            uint32_t bkoff = (uint32_t)(c * 16 + b_k8) * 2;
            uint32_t ah[2][4], al[2][4];
            #pragma unroll
            for (int mt = 0; mt < 2; mt++) {
                uint32_t ra = stbase + (uint32_t)(wm + mt * 16 + a_row) * 80 + akoff;
                LDSM_X4(ah[mt], ra + OFF_AH);
                LDSM_X4(al[mt], ra + OFF_AL);
            }
            #pragma unroll
            for (int ntp = 0; ntp < 4; ntp++) {
                uint32_t rb = stbase + (uint32_t)(wn + ntp * 16 + b_row) * 80 + bkoff;
                uint32_t bh[4], bl[4];
                LDSM_X4(bh, rb + OFF_BH);
                LDSM_X4(bl, rb + OFF_BL);
                #pragma unroll
                for (int sub = 0; sub < 2; sub++) {
                    #pragma unroll
                    for (int mt = 0; mt < 2; mt++) {
                        float* d = acc[mt][ntp * 2 + sub];
                        MMA16816(d, ah[mt], bh[sub * 2], bh[sub * 2 + 1]);
                        MMA16816(d, ah[mt], bl[sub * 2], bl[sub * 2 + 1]);
                        MMA16816(d, al[mt], bh[sub * 2], bh[sub * 2 + 1]);
                    }
                }
            }
        }
    }

    const float* bias = ball + layer * NDIM;
    #pragma unroll
    for (int mt = 0; mt < 2; mt++) {
        #pragma unroll
        for (int hrow = 0; hrow < 2; hrow++) {
            int row = m0 + wm + mt * 16 + (lane >> 2) + hrow * 8;
            #pragma unroll
            for (int nt = 0; nt < 8; nt++) {
                int col = n0 + wn + nt * 8 + (lane & 3) * 2;
                if (col < NDIM) {
                    float v0 = fmaxf(acc[mt][nt][hrow * 2 + 0] + __ldg(bias + col), 0.f);
                    float v1 = fmaxf(acc[mt][nt][hrow * 2 + 1] + __ldg(bias + col + 1), 0.f);
                    uint32_t hi, lo;
                    split2(v0, v1, hi, lo);
                    *(uint32_t*)(g_hidh + (size_t)row * KP2 + col) = hi;
                    *(uint32_t*)(g_hidl + (size_t)row * KP2 + col) = lo;
                }
            }
        }
    }
}

// ---------------------------------------------------------------------------
// GEMM2: 256x64 tile, 256 threads, 8 M-warps, fp32 out + fused BN partials.
// ---------------------------------------------------------------------------
#define STG2_BYTES 51200
#define OFF2_AH 0
#define OFF2_AL 20480
#define OFF2_BH 40960
#define OFF2_BL 46080
#define GEMM2_SMEM (2 * STG2_BYTES)

__global__ void __launch_bounds__(256, 2) gemm2_kernel(const float* __restrict__ ball,
                                                       int layer) {
    constexpr int NDIM = EMB, KPAD = KP2, NPAD = NP2, NKB = KP2 / 32;

    extern __shared__ __align__(16) char sm[];
    uint32_t sb = smem_u32(sm);

    int tid  = threadIdx.x;
    int lane = tid & 31;
    int wid  = tid >> 5;
    int wm   = wid * 32;
    int m0   = blockIdx.x * 256;
    int n0   = blockIdx.y * 64;

    int lg = lane >> 3, lj = lane & 7;
    int a_row = (lg & 1) * 8 + lj;
    int a_k8  = (lg >> 1) * 8;
    int b_row = (lg >> 1) * 8 + lj;
    int b_k8  = (lg & 1) * 8;

    float acc[2][8][4];
    #pragma unroll
    for (int mt = 0; mt < 2; mt++)
        #pragma unroll
        for (int nt = 0; nt < 8; nt++)
            #pragma unroll
            for (int q = 0; q < 4; q++) acc[mt][nt][q] = 0.f;

    const size_t bbase = ((size_t)layer * NPAD + n0) * KPAD;

    auto issue = [&](int kb, int st) {
        uint32_t base = sb + st * STG2_BYTES;
        #pragma unroll
        for (int i = 0; i < 10; i++) {
            int v = tid + i * 256;
            if (v < 2048) {
                int arr = v >> 10;
                int rem = v & 1023;
                int r = rem >> 2, c = rem & 3;
                uint32_t so = (arr ? OFF2_AL : OFF2_AH) + r * 80 + c * 16;
                size_t ga = (size_t)(m0 + r) * KPAD + kb * 32 + c * 8;
                cpa16(base + so, (arr ? g_hidl : g_hidh) + ga);
            } else {
                int v2 = v - 2048;
                int arr = v2 >> 8;
                int rem = v2 & 255;
                int r = rem >> 2, c = rem & 3;
                uint32_t so = (arr ? OFF2_BL : OFF2_BH) + r * 80 + c * 16;
                size_t gb = bbase + (size_t)r * KPAD + kb * 32 + c * 8;
                cpa16(base + so, (arr ? g_w2l : g_w2h) + gb);
            }
        }
        CPA_COMMIT();
    };

    issue(0, 0);

    for (int kb = 0; kb < NKB; kb++) {
        int st = kb & 1;
        CPA_WAIT(0);
        __syncthreads();
        if (kb + 1 < NKB) issue(kb + 1, st ^ 1);

        uint32_t stbase = sb + st * STG2_BYTES;
        #pragma unroll
        for (int c = 0; c < 2; c++) {
            uint32_t akoff = (uint32_t)(c * 16 + a_k8) * 2;
            uint32_t bkoff = (uint32_t)(c * 16 + b_k8) * 2;
            uint32_t ah[2][4], al[2][4];
            #pragma unroll
            for (int mt = 0; mt < 2; mt++) {
                uint32_t ra = stbase + (uint32_t)(wm + mt * 16 + a_row) * 80 + akoff;
                LDSM_X4(ah[mt], ra + OFF2_AH);
                LDSM_X4(al[mt], ra + OFF2_AL);
            }
            #pragma unroll
            for (int ntp = 0; ntp < 4; ntp++) {
                uint32_t rb = stbase + (uint32_t)(ntp * 16 + b_row) * 80 + bkoff;
                uint32_t bh[4], bl[4];
                LDSM_X4(bh, rb + OFF2_BH);
                LDSM_X4(bl, rb + OFF2_BL);
                #pragma unroll
                for (int sub = 0; sub < 2; sub++) {
                    #pragma unroll
                    for (int mt = 0; mt < 2; mt++) {
                        float* d = acc[mt][ntp * 2 + sub];
                        MMA16816(d, ah[mt], bh[sub * 2], bh[sub * 2 + 1]);
                        MMA16816(d, ah[mt], bl[sub * 2], bl[sub * 2 + 1]);
                        MMA16816(d, al[mt], bh[sub * 2], bh[sub * 2 + 1]);
                    }
                }
            }
        }
    }

    __syncthreads();
    float* red = (float*)sm;
    const float* bias = ball + layer * NDIM;

    #pragma unroll
    for (int nt = 0; nt < 8; nt++) {
        int col = n0 + nt * 8 + (lane & 3) * 2;
        float bv0 = (col     < NDIM) ? __ldg(bias + col)     : 0.f;
        float bv1 = (col + 1 < NDIM) ? __ldg(bias + col + 1) : 0.f;
        float s0 = 0.f, q0 = 0.f, s1 = 0.f, q1 = 0.f;
        #pragma unroll
        for (int mt = 0; mt < 2; mt++) {
            #pragma unroll
            for (int hrow = 0; hrow < 2; hrow++) {
                int row = m0 + wm + mt * 16 + (lane >> 2) + hrow * 8;
                float v0 = acc[mt][nt][hrow * 2 + 0] + bv0;
                float v1 = acc[mt][nt][hrow * 2 + 1] + bv1;
                if (col < NDIM) {
                    float2 stv; stv.x = v0; stv.y = v1;
                    *(float2*)(g_agg + (size_t)row * EMB + col) = stv;
                }
                if (row < N_NODES) {
                    s0 += v0; q0 += v0 * v0;
                    s1 += v1; q1 += v1 * v1;
                }
            }
        }
        #pragma unroll
        for (int d = 4; d < 32; d <<= 1) {
            s0 += __shfl_xor_sync(0xffffffffu, s0, d);
            q0 += __shfl_xor_sync(0xffffffffu, q0, d);
            s1 += __shfl_xor_sync(0xffffffffu, s1, d);
            q1 += __shfl_xor_sync(0xffffffffu, q1, d);
        }
        if (lane < 4) {
            float* p = red + ((wid * 8 + nt) * 4 + lane) * 4;
            p[0] = s0; p[1] = q0; p[2] = s1; p[3] = q1;
        }
    }
    __syncthreads();
    if (tid < 32) {
        int nt = tid >> 2, L = tid & 3;
        float s0 = 0.f, q0 = 0.f, s1 = 0.f, q1 = 0.f;
        #pragma unroll
        for (int w = 0; w < 8; w++) {
            const float* p = red + ((w * 8 + nt) * 4 + L) * 4;
            s0 += p[0]; q0 += p[1]; s1 += p[2]; q1 += p[3];
        }
        int col = n0 + nt * 8 + L * 2;
        int bx = blockIdx.x;
        if (col < NDIM) {
            g_part[bx * 2 * EMB + col]       = s0;
            g_part[bx * 2 * EMB + EMB + col] = q0;
        }
        if (col + 1 < NDIM) {
            g_part[bx * 2 * EMB + col + 1]       = s1;
            g_part[bx * 2 * EMB + EMB + col + 1] = q1;
        }
    }
}

// ---------------------------------------------------------------------------
// bn_final: 960 threads, 3-way fixed chunk partition + fixed-order combine.
// Deterministic (same grouping every run).
// ---------------------------------------------------------------------------
__global__ void bn_final_kernel(const float* __restrict__ gamma,
                                const float* __restrict__ beta, int layer) {
    __shared__ float sS[3 * 320];
    __shared__ float sQ[3 * 320];
    int tid = threadIdx.x;            // 960
    int c = tid % 320;
    int p = tid / 320;                // 0..2
    float s = 0.f, q = 0.f;
    if (c < EMB) {
        int b0 = p * 66;
        int b1 = min(b0 + 66, NCHUNK);
        for (int b = b0; b < b1; b++) {
            s += g_part[b * 2 * EMB + c];
            q += g_part[b * 2 * EMB + EMB + c];
        }
    }
    sS[p * 320 + c] = s;
    sQ[p * 320 + c] = q;
    __syncthreads();
    if (tid < EMB) {
        float ss = (sS[tid] + sS[320 + tid]) + sS[640 + tid];
        float qq = (sQ[tid] + sQ[320 + tid]) + sQ[640 + tid];
        const float inv_n = 1.0f / (float)N_NODES;
        float mean = ss * inv_n;
        float var  = qq * inv_n - mean * mean;
        float sc = gamma[layer * EMB + tid] * rsqrtf(var + 1e-5f);
        float sh = beta[layer * EMB + tid] - mean * sc;
        g_stats[tid]       = sc;
        g_stats[EMB + tid] = sh;
    }
}
__global__ void bn_apply_kernel(float* __restrict__ dst) {     // final layer
    int idx = blockIdx.x * blockDim.x + threadIdx.x;
    if (idx >= N_NODES * 75) return;
    int c = (idx % 75) * 4;
    float4 v = ((const float4*)g_agg)[idx];
    float4 r;
    r.x = v.x * g_stats[c + 0] + g_stats[EMB + c + 0];
    r.y = v.y * g_stats[c + 1] + g_stats[EMB + c + 1];
    r.z = v.z * g_stats[c + 2] + g_stats[EMB + c + 2];
    r.w = v.w * g_stats[c + 3] + g_stats[EMB + c + 3];
    ((float4*)dst)[idx] = r;
}

// ---------------------------------------------------------------------------
extern "C" void kernel_launch(void* const* d_in, const int* in_sizes, int n_in,
                              void* d_out, int out_size) {
    const int*   x     = (const int*)d_in[0];
    const int*   ei    = (const int*)d_in[1];
    const int*   ea    = (const int*)d_in[2];
    const float* xemb  = (const float*)d_in[3];
    const float* eemb  = (const float*)d_in[4];
    const float* W1    = (const float*)d_in[5];
    const float* b1    = (const float*)d_in[6];
    const float* W2    = (const float*)d_in[7];
    const float* b2    = (const float*)d_in[8];
    const float* gamma = (const float*)d_in[9];
    const float* beta  = (const float*)d_in[10];
    float* out = (float*)d_out;

    cudaFuncSetAttribute(gemm1_kernel,
                         cudaFuncAttributeMaxDynamicSharedMemorySize, GEMM1_SMEM);
    cudaFuncSetAttribute(gemm2_kernel,
                         cudaFuncAttributeMaxDynamicSharedMemorySize, GEMM2_SMEM);

    node_emb_kernel<<<(N_NODES * 75 + 255) / 256, 256>>>(x, xemb);
    prep_w1_kernel<<<(NLAYER * NP1 * KP1 + 255) / 256, 256>>>(W1);
    prep_w2_kernel<<<(NLAYER * NP2 * KP2 + 255) / 256, 256>>>(W2);

    reset_kernel<<<(N_NODES + 255) / 256, 256>>>();
    hist_kernel<<<(N_EDGES + 255) / 256, 256>>>(ei, ea);
    scan1_kernel<<<NBLK256, 256>>>();
    scan2_kernel<<<1, 256>>>();
    scan3_kernel<<<NBLK256, 256>>>();
    fill_kernel<<<(N_EDGES + 255) / 256, 256>>>(ei);
    sort_kernel<<<(N_NODES + 255) / 256, 256>>>();

    float* hsrc_first;
    cudaGetSymbolAddress((void**)&hsrc_first, g_h);
    float* hsrc_rest;
    cudaGetSymbolAddress((void**)&hsrc_rest, g_agg);

    const int ggrid = (N_NODES + GNODES - 1) / GNODES;
    for (int layer = 0; layer < NLAYER; layer++) {
        if (layer == 0)
            gather_kernel<false><<<ggrid, 160>>>(hsrc_first, eemb, layer);
        else
            gather_kernel<true ><<<ggrid, 160>>>(hsrc_rest, eemb, layer);
        gemm1_kernel<<<dim3(M_PAD / 128, NP1 / 128), 256, GEMM1_SMEM>>>(b1, layer);
        gemm2_kernel<<<dim3(M_PAD / 256, NP2 / 64), 256, GEMM2_SMEM>>>(b2, layer);
        bn_final_kernel<<<1, 960>>>(gamma, beta, layer);
    }
    bn_apply_kernel<<<(N_NODES * 75 + 255) / 256, 256>>>(out);
}